// round 6
// baseline (speedup 1.0000x reference)
#include <cuda_runtime.h>
#include <cuda_fp16.h>
#include <mma.h>
#include <cstdint>

using namespace nvcuda;

#define D   512
#define E   16
#define H1  128
#define H2  64
#define R   32
#define C1  (E * H1)   // 2048
#define C2  (E * H2)   // 1024
#define NMAX 65536

// ---------------- scratch (device globals: allocation-free) ----------------
__device__ __half g_x16[(size_t)NMAX * D];        // 64 MB
__device__ __half g_W1h[(size_t)E * D * H1];      // 2 MB   [e][d][j]
__device__ __half g_W2h[(size_t)E * H1 * H2];     // 256 KB [e][k][j]
__device__ __half g_h2[(size_t)NMAX * C2];        // 128 MB
__device__ float  g_gate[(size_t)NMAX * E];       // 4 MB
__device__ float  g_G[512 * 512];                 // 1 MB Gram = X^T X (raw sums)
__device__ float  g_colsum[512];
__device__ float  g_mean1[C1], g_inv1[C1];
__device__ float  g_sum2[C2], g_ssq2[C2], g_mean2[C2], g_inv2[C2];
__device__ float  g_v[C2];

// ---------------- cp.async helpers ----------------
__device__ __forceinline__ void cp_async16(void* smem, const void* gmem) {
    unsigned int s = (unsigned int)__cvta_generic_to_shared(smem);
    asm volatile("cp.async.cg.shared.global [%0], [%1], 16;\n" :: "r"(s), "l"(gmem));
}
__device__ __forceinline__ void cp_commit() {
    asm volatile("cp.async.commit_group;\n");
}
template <int NN>
__device__ __forceinline__ void cp_wait() {
    asm volatile("cp.async.wait_group %0;\n" :: "n"(NN));
}

// ---------------- 0: pack weights fp16 + zero accumulators ----------------
__global__ void __launch_bounds__(256) pack_W_zero(const float* __restrict__ W1,
                                                   const float* __restrict__ W2) {
    int idx = blockIdx.x * 256 + threadIdx.x;   // grid 4608 -> 1179648
    if (idx < E * D * H1) g_W1h[idx] = __float2half_rn(W1[idx]);
    if (idx < E * H1 * H2) g_W2h[idx] = __float2half_rn(W2[idx]);
    if (idx < 512 * 512) g_G[idx] = 0.f;
    if (idx < 512) g_colsum[idx] = 0.f;
    if (idx < C2) { g_sum2[idx] = 0.f; g_ssq2[idx] = 0.f; }
}

// ---------------- 1: convert x -> fp16, column sums, gating ----------------
__global__ void __launch_bounds__(256) convert_gate(
    const float* __restrict__ x, const float* __restrict__ Wg,
    const float* __restrict__ bg, const float* __restrict__ gamma_,
    const float* __restrict__ beta_) {
    __shared__ float xs[16 * D];   // 32 KB
    const int tid = threadIdx.x;
    const size_t row0 = (size_t)blockIdx.x * 16;

    const float4* xg = reinterpret_cast<const float4*>(x + row0 * D);
    float4* xsv = reinterpret_cast<float4*>(xs);
    __half* xo = g_x16 + row0 * D;
#pragma unroll
    for (int i = 0; i < 8; ++i) {
        int c = tid + i * 256;          // 0..2047 float4s
        float4 v = xg[c];
        xsv[c] = v;
        __half2 h0 = __floats2half2_rn(v.x, v.y);
        __half2 h1 = __floats2half2_rn(v.z, v.w);
        *reinterpret_cast<__half2*>(xo + 4 * c) = h0;
        *reinterpret_cast<__half2*>(xo + 4 * c + 2) = h1;
    }
    __syncthreads();

    // column sums (2 columns per thread, 16 rows each)
    {
        int c0 = tid * 2;
        float s0 = 0.f, s1 = 0.f;
#pragma unroll
        for (int r = 0; r < 16; ++r) {
            s0 += xs[r * D + c0];
            s1 += xs[r * D + c0 + 1];
        }
        atomicAdd(&g_colsum[c0], s0);
        atomicAdd(&g_colsum[c0 + 1], s1);
    }

    // gating
    const int e = tid & 15, r = tid >> 4;
    float g = 0.f;
#pragma unroll 8
    for (int d = 0; d < D; ++d) g += xs[r * D + d] * Wg[d * E + e];
    g += bg[e];

    float mu = g;
#pragma unroll
    for (int o = 8; o; o >>= 1) mu += __shfl_xor_sync(0xffffffffu, mu, o, 16);
    mu *= (1.f / 16.f);
    float dv = g - mu;
    float vv = dv * dv;
#pragma unroll
    for (int o = 8; o; o >>= 1) vv += __shfl_xor_sync(0xffffffffu, vv, o, 16);
    vv *= (1.f / 16.f);
    g = dv * rsqrtf(vv + 1e-5f) * gamma_[e] + beta_[e];

    float mx = g;
#pragma unroll
    for (int o = 8; o; o >>= 1) mx = fmaxf(mx, __shfl_xor_sync(0xffffffffu, mx, o, 16));
    float ex = __expf(g - mx);
    float s = ex;
#pragma unroll
    for (int o = 8; o; o >>= 1) s += __shfl_xor_sync(0xffffffffu, s, o, 16);
    g_gate[(row0 + r) * E + e] = ex / s;
}

// ---------------- 2: Gram G = X^T X (upper-triangular tiles, split-K) ----------------
// grid (10, 32): blockIdx.x = upper tile id, blockIdx.y = K split (2048 rows each)
__device__ __constant__ int c_ti[10] = {0, 0, 0, 0, 1, 1, 1, 2, 2, 3};
__device__ __constant__ int c_tj[10] = {0, 1, 2, 3, 1, 2, 3, 2, 3, 3};

#define GR_STAGE 34816                      // Xi(17408) + Xj(17408)
#define GR_SMEM  (2 * GR_STAGE)             // 69632; Cs fp32 128x132 = 67584 fits

__global__ void __launch_bounds__(256, 2) gram_kernel() {
    extern __shared__ char smbuf[];
    const int ti = c_ti[blockIdx.x];
    const int tj = c_tj[blockIdx.x];
    const int sK = blockIdx.y * 2048;
    const int tid = threadIdx.x;
    const int warp = tid >> 5;
    const int wm = warp & 3;     // 4 over rows
    const int wn = warp >> 2;    // 2 over cols

    wmma::fragment<wmma::accumulator, 16, 16, 16, float> acc[2][4];
#pragma unroll
    for (int i = 0; i < 2; ++i)
#pragma unroll
        for (int j = 0; j < 4; ++j) wmma::fill_fragment(acc[i][j], 0.0f);

    auto issue = [&](int kt, int s) {
        const int n0 = sK + kt * 64;
        __half* Xi = reinterpret_cast<__half*>(smbuf + s * GR_STAGE);
        __half* Xj = Xi + 8704;
#pragma unroll
        for (int i = 0; i < 8; ++i) {
            int c = tid + i * 256;               // 0..2047
            int panel = c >> 10;
            int cc = c & 1023;
            int row = cc >> 4, off = (cc & 15) * 8;
            __half* dst = (panel ? Xj : Xi) + row * 136 + off;
            int t = panel ? tj : ti;
            cp_async16(dst, g_x16 + (size_t)(n0 + row) * D + t * 128 + off);
        }
        cp_commit();
    };

    issue(0, 0);
    issue(1, 1);

    for (int kt = 0; kt < 32; ++kt) {
        const int cur = kt & 1;
        if (kt < 31) cp_wait<1>(); else cp_wait<0>();
        __syncthreads();

        const __half* Xi = reinterpret_cast<const __half*>(smbuf + cur * GR_STAGE);
        const __half* Xj = Xi + 8704;
#pragma unroll
        for (int kk = 0; kk < 4; ++kk) {
            wmma::fragment<wmma::matrix_a, 16, 16, 16, __half, wmma::col_major> af[2];
            wmma::fragment<wmma::matrix_b, 16, 16, 16, __half, wmma::row_major> bf[4];
#pragma unroll
            for (int i = 0; i < 2; ++i)
                wmma::load_matrix_sync(af[i], Xi + (kk * 16) * 136 + wm * 32 + i * 16, 136);
#pragma unroll
            for (int j = 0; j < 4; ++j)
                wmma::load_matrix_sync(bf[j], Xj + (kk * 16) * 136 + wn * 64 + j * 16, 136);
#pragma unroll
            for (int i = 0; i < 2; ++i)
#pragma unroll
                for (int j = 0; j < 4; ++j)
                    wmma::mma_sync(acc[i][j], af[i], bf[j], acc[i][j]);
        }
        __syncthreads();
        if (kt + 2 < 32) issue(kt + 2, cur);
    }

    __syncthreads();
    float* Cs = reinterpret_cast<float*>(smbuf);   // [128][132]
#pragma unroll
    for (int i = 0; i < 2; ++i)
#pragma unroll
        for (int j = 0; j < 4; ++j)
            wmma::store_matrix_sync(Cs + (wm * 32 + i * 16) * 132 + wn * 64 + j * 16,
                                    acc[i][j], 132, wmma::mem_row_major);
    __syncthreads();

#pragma unroll
    for (int i = 0; i < 64; ++i) {
        int idx = tid + i * 256;
        int r = idx >> 7, c = idx & 127;
        atomicAdd(&g_G[(ti * 128 + r) * 512 + tj * 128 + c], Cs[r * 132 + c]);
    }
}

// ---------------- 3: mirror lower triangle ----------------
__global__ void mirror_G() {
    int idx = blockIdx.x * 256 + threadIdx.x;   // grid 1024
    int d = idx >> 9, dp = idx & 511;
    if (dp < d) g_G[idx] = g_G[dp * 512 + d];
}

// ---------------- 4: BN1 stats from Gram: mean1, inv1 ----------------
// grid (16, 4): expert e, column group of 32
#define S1_SMEM (512 * 33 * 4 + 512 * 4 + 2 * 256 * 4)   // 71680

__global__ void __launch_bounds__(256) stats1_kernel(float invN) {
    extern __shared__ char smbuf[];
    float* ws = reinterpret_cast<float*>(smbuf);            // [512][33]
    float* cs = reinterpret_cast<float*>(smbuf + 67584);    // [512]
    float* redE = reinterpret_cast<float*>(smbuf + 69632);  // [256]
    float* redM = redE + 256;

    const int e = blockIdx.x, cg = blockIdx.y;
    const int tid = threadIdx.x;

#pragma unroll
    for (int i = 0; i < 64; ++i) {
        int c = tid + i * 256;       // 0..16383
        int d = c >> 5, jj = c & 31;
        ws[d * 33 + jj] = __half2float(g_W1h[(size_t)e * (D * H1) + d * H1 + cg * 32 + jj]);
    }
    cs[tid] = g_colsum[tid];
    cs[tid + 256] = g_colsum[tid + 256];
    __syncthreads();

    const int jj = tid & 31, dg = tid >> 5;
    float accE = 0.f, accM = 0.f;
    for (int d = dg * 64; d < dg * 64 + 64; ++d) {
        float wd = ws[d * 33 + jj];
        float td = 0.f;
        const float4* Gr = reinterpret_cast<const float4*>(g_G + d * 512);
#pragma unroll 4
        for (int q = 0; q < 128; ++q) {
            float4 g4 = Gr[q];
            td = fmaf(g4.x, ws[(4 * q + 0) * 33 + jj], td);
            td = fmaf(g4.y, ws[(4 * q + 1) * 33 + jj], td);
            td = fmaf(g4.z, ws[(4 * q + 2) * 33 + jj], td);
            td = fmaf(g4.w, ws[(4 * q + 3) * 33 + jj], td);
        }
        accE = fmaf(wd, td, accE);
        accM = fmaf(wd, cs[d], accM);
    }
    redE[tid] = accE;
    redM[tid] = accM;
    __syncthreads();

    if (tid < 32) {
        float Es = 0.f, Ms = 0.f;
#pragma unroll
        for (int g2 = 0; g2 < 8; ++g2) { Es += redE[g2 * 32 + tid]; Ms += redM[g2 * 32 + tid]; }
        float mean = Ms * invN;
        float var = fmaxf(Es * invN - mean * mean, 0.f);
        int col = e * H1 + cg * 32 + tid;
        g_mean1[col] = mean;
        g_inv1[col] = rsqrtf(var + 1e-4f);
    }
}

// ---------------- 5: FUSED GEMM1 -> BN1+LReLU -> GEMM2 (+BN2 stats) ----------------
// grid (16, 512): blockIdx.x = expert (fastest, shares x tile in L2), blockIdx.y = mtile.
// smem: stages 2x(Ax 128x72 + Bw 64x136) = 71680, W2s 18432, Ah 18432, stats 1024.
#define F_STAGE 35840
#define F_W2    71680
#define F_AH    90112
#define F_STAT  108544
#define F_SMEM  109568

__global__ void __launch_bounds__(256, 2) gemm12_kernel() {
    extern __shared__ char smbuf[];
    const int e = blockIdx.x;
    const size_t m0 = (size_t)blockIdx.y * 128;
    const int tid = threadIdx.x;
    const int warp = tid >> 5;
    const int wm = warp & 3;
    const int wn = warp >> 2;

    wmma::fragment<wmma::accumulator, 16, 16, 16, float> acc[2][4];
#pragma unroll
    for (int i = 0; i < 2; ++i)
#pragma unroll
        for (int j = 0; j < 4; ++j) wmma::fill_fragment(acc[i][j], 0.0f);

    auto issue = [&](int kt, int s) {
        const int k0 = kt * 64;
        __half* Ax = reinterpret_cast<__half*>(smbuf + s * F_STAGE);
        __half* Bw = Ax + 9216;   // 18432 bytes
#pragma unroll
        for (int i = 0; i < 4; ++i) {
            int c = tid + i * 256;
            int r = c >> 3, off = (c & 7) * 8;
            cp_async16(Ax + r * 72 + off, g_x16 + (m0 + r) * D + k0 + off);
        }
#pragma unroll
        for (int i = 0; i < 4; ++i) {
            int c = tid + i * 256;
            int r = c >> 4, off = (c & 15) * 8;
            cp_async16(Bw + r * 136 + off,
                       g_W1h + (size_t)e * (D * H1) + (size_t)(k0 + r) * H1 + off);
        }
        cp_commit();
    };

    // prologue: W2 tile (joins group 0) + stages 0,1
    {
        __half* W2s = reinterpret_cast<__half*>(smbuf + F_W2);
#pragma unroll
        for (int i = 0; i < 4; ++i) {
            int c = tid + i * 256;
            int r = c >> 3, off = (c & 7) * 8;
            cp_async16(W2s + r * 72 + off, g_W2h + (size_t)e * (H1 * H2) + r * H2 + off);
        }
    }
    issue(0, 0);
    issue(1, 1);

    // BN1 stats into smem
    float* ms = reinterpret_cast<float*>(smbuf + F_STAT);
    float* is = ms + 128;
    if (tid < 128) {
        ms[tid] = g_mean1[e * H1 + tid];
        is[tid] = g_inv1[e * H1 + tid];
    }

    for (int kt = 0; kt < 8; ++kt) {
        const int cur = kt & 1;
        if (kt < 7) cp_wait<1>(); else cp_wait<0>();
        __syncthreads();

        const __half* Ax = reinterpret_cast<const __half*>(smbuf + cur * F_STAGE);
        const __half* Bw = Ax + 9216;
#pragma unroll
        for (int kk = 0; kk < 4; ++kk) {
            wmma::fragment<wmma::matrix_a, 16, 16, 16, __half, wmma::row_major> af[2];
            wmma::fragment<wmma::matrix_b, 16, 16, 16, __half, wmma::row_major> bf[4];
#pragma unroll
            for (int i = 0; i < 2; ++i)
                wmma::load_matrix_sync(af[i], Ax + (wm * 32 + i * 16) * 72 + kk * 16, 72);
#pragma unroll
            for (int j = 0; j < 4; ++j)
                wmma::load_matrix_sync(bf[j], Bw + (kk * 16) * 136 + wn * 64 + j * 16, 136);
#pragma unroll
            for (int i = 0; i < 2; ++i)
#pragma unroll
                for (int j = 0; j < 4; ++j)
                    wmma::mma_sync(acc[i][j], af[i], bf[j], acc[i][j]);
        }
        __syncthreads();
        if (kt + 2 < 8) issue(kt + 2, cur);
    }

    // ---- h1 (fp32) -> Cs in smem ----
    __syncthreads();
    float* Cs = reinterpret_cast<float*>(smbuf);   // [128][132]
#pragma unroll
    for (int i = 0; i < 2; ++i)
#pragma unroll
        for (int j = 0; j < 4; ++j)
            wmma::store_matrix_sync(Cs + (wm * 32 + i * 16) * 132 + wn * 64 + j * 16,
                                    acc[i][j], 132, wmma::mem_row_major);
    __syncthreads();

    // ---- GEMM2: bn_lrelu(h1) @ W2, K=128 in 2 halves of 64 ----
    wmma::fragment<wmma::accumulator, 16, 16, 16, float> acc2[2][2];
#pragma unroll
    for (int i = 0; i < 2; ++i)
#pragma unroll
        for (int j = 0; j < 2; ++j) wmma::fill_fragment(acc2[i][j], 0.0f);

    __half* Ah = reinterpret_cast<__half*>(smbuf + F_AH);
    const __half* W2s = reinterpret_cast<const __half*>(smbuf + F_W2);

#pragma unroll
    for (int kh = 0; kh < 2; ++kh) {
        // convert+BN+lrelu 128x64 columns [kh*64, kh*64+64)
#pragma unroll
        for (int i = 0; i < 16; ++i) {
            int pid = tid + i * 256;         // 0..4095 half2 pairs
            int r = pid >> 5, c2 = pid & 31;
            int col = kh * 64 + 2 * c2;
            float v0 = Cs[r * 132 + col];
            float v1 = Cs[r * 132 + col + 1];
            float a0 = (v0 - ms[col]) * is[col];
            float a1 = (v1 - ms[col + 1]) * is[col + 1];
            a0 = (a0 >= 0.f) ? a0 : 0.01f * a0;
            a1 = (a1 >= 0.f) ? a1 : 0.01f * a1;
            *reinterpret_cast<__half2*>(Ah + r * 72 + 2 * c2) = __floats2half2_rn(a0, a1);
        }
        __syncthreads();

#pragma unroll
        for (int kk = 0; kk < 4; ++kk) {
            wmma::fragment<wmma::matrix_a, 16, 16, 16, __half, wmma::row_major> af2[2];
            wmma::fragment<wmma::matrix_b, 16, 16, 16, __half, wmma::row_major> bf2[2];
#pragma unroll
            for (int i = 0; i < 2; ++i)
                wmma::load_matrix_sync(af2[i], Ah + (wm * 32 + i * 16) * 72 + kk * 16, 72);
#pragma unroll
            for (int j = 0; j < 2; ++j)
                wmma::load_matrix_sync(bf2[j],
                                       W2s + (kh * 64 + kk * 16) * 72 + wn * 32 + j * 16, 72);
#pragma unroll
            for (int i = 0; i < 2; ++i)
#pragma unroll
                for (int j = 0; j < 2; ++j)
                    wmma::mma_sync(acc2[i][j], af2[i], bf2[j], acc2[i][j]);
        }
        __syncthreads();
    }

    // ---- epilogue: h2 stats + fp16 store ----
    float* Cs2 = reinterpret_cast<float*>(smbuf);  // [128][68]
#pragma unroll
    for (int i = 0; i < 2; ++i)
#pragma unroll
        for (int j = 0; j < 2; ++j)
            wmma::store_matrix_sync(Cs2 + (wm * 32 + i * 16) * 68 + wn * 32 + j * 16,
                                    acc2[i][j], 68, wmma::mem_row_major);
    __syncthreads();

    {
        int c = tid & 63, q4 = tid >> 6;
        float s = 0.f, q = 0.f;
#pragma unroll 8
        for (int r = q4 * 32; r < q4 * 32 + 32; ++r) {
            float v = Cs2[r * 68 + c];
            s += v;
            q = fmaf(v, v, q);
        }
        atomicAdd(&g_sum2[e * H2 + c], s);
        atomicAdd(&g_ssq2[e * H2 + c], q);
    }

#pragma unroll
    for (int i = 0; i < 16; ++i) {
        int pid = tid + i * 256;
        int r = pid >> 5, c2 = pid & 31;
        __half2 h = __floats2half2_rn(Cs2[r * 68 + 2 * c2], Cs2[r * 68 + 2 * c2 + 1]);
        *reinterpret_cast<__half2*>(g_h2 + (m0 + r) * C2 + e * H2 + 2 * c2) = h;
    }
}

// ---------------- 6: finalize BN2 stats + v = W3 @ Ws ----------------
__global__ void __launch_bounds__(256) finalize2(const float* __restrict__ W3,
                                                 const float* __restrict__ Ws, float invN) {
    __shared__ float wsm[R];
    const int tid = threadIdx.x;
    const int i = blockIdx.x * 256 + tid;   // grid 4 -> 0..1023 = e*64+k
    if (tid < R) wsm[tid] = Ws[tid];
    __syncthreads();

    float v = 0.f;
#pragma unroll
    for (int r = 0; r < R; ++r) v = fmaf(W3[(size_t)i * R + r], wsm[r], v);
    g_v[i] = v;

    float mean = g_sum2[i] * invN;
    float var = fmaxf(g_ssq2[i] * invN - mean * mean, 0.f);
    g_mean2[i] = mean;
    g_inv2[i] = rsqrtf(var + 1e-4f);
}

// ---------------- 7: final combine ----------------
__global__ void __launch_bounds__(256) final_kernel(const float* __restrict__ bs_p,
                                                    float* __restrict__ out) {
    const int tid = threadIdx.x;
    const int e = tid & 15, r = tid >> 4;
    const size_t row = (size_t)blockIdx.x * 16 + r;

    const uint4* hp = reinterpret_cast<const uint4*>(g_h2 + row * C2 + (size_t)e * H2);
    const float* mp = g_mean2 + e * H2;
    const float* ip = g_inv2 + e * H2;
    const float* vp = g_v + e * H2;

    float acc = 0.f;
#pragma unroll
    for (int i = 0; i < 8; ++i) {      // 8 uint4 = 64 halves (BUGFIX: was 4)
        uint4 q = hp[i];
        unsigned vals[4] = {q.x, q.y, q.z, q.w};
#pragma unroll
        for (int j = 0; j < 4; ++j) {
            __half2 h2 = *reinterpret_cast<__half2*>(&vals[j]);
            float2 f = __half22float2(h2);
            int k = i * 8 + j * 2;
            float a0 = (f.x - mp[k]) * ip[k];
            float a1 = (f.y - mp[k + 1]) * ip[k + 1];
            a0 = (a0 >= 0.f) ? a0 : 0.01f * a0;
            a1 = (a1 >= 0.f) ? a1 : 0.01f * a1;
            acc = fmaf(a0, vp[k], acc);
            acc = fmaf(a1, vp[k + 1], acc);
        }
    }
    float contrib = g_gate[row * E + e] * (acc + bs_p[0]);
#pragma unroll
    for (int o = 8; o; o >>= 1) contrib += __shfl_down_sync(0xffffffffu, contrib, o, 16);
    if (e == 0) out[row] = contrib;
}

// ---------------- launch ----------------
extern "C" void kernel_launch(void* const* d_in, const int* in_sizes, int n_in,
                              void* d_out, int out_size) {
    const float* x  = (const float*)d_in[0];
    const float* Wg = (const float*)d_in[1];
    const float* bg = (const float*)d_in[2];
    const float* ga = (const float*)d_in[3];
    const float* be = (const float*)d_in[4];
    const float* W1 = (const float*)d_in[5];
    const float* W2 = (const float*)d_in[6];
    const float* W3 = (const float*)d_in[7];
    const float* Ws = (const float*)d_in[8];
    const float* bs = (const float*)d_in[9];
    float* out = (float*)d_out;

    const int N = in_sizes[0] / D;        // 65536
    const int mtiles = N / 128;           // 512
    const float invN = 1.0f / (float)N;

    static bool attr_done = false;
    if (!attr_done) {
        cudaFuncSetAttribute(gram_kernel, cudaFuncAttributeMaxDynamicSharedMemorySize, GR_SMEM);
        cudaFuncSetAttribute(stats1_kernel, cudaFuncAttributeMaxDynamicSharedMemorySize, S1_SMEM);
        cudaFuncSetAttribute(gemm12_kernel, cudaFuncAttributeMaxDynamicSharedMemorySize, F_SMEM);
        attr_done = true;
    }

    pack_W_zero<<<4608, 256>>>(W1, W2);                           // 0
    convert_gate<<<N / 16, 256>>>(x, Wg, bg, ga, be);             // 1
    gram_kernel<<<dim3(10, 32), 256, GR_SMEM>>>();                // 2
    mirror_G<<<1024, 256>>>();                                    // 3
    stats1_kernel<<<dim3(E, 4), 256, S1_SMEM>>>(invN);            // 4
    gemm12_kernel<<<dim3(E, mtiles), 256, F_SMEM>>>();            // 5 (profiled slot)
    finalize2<<<C2 / 256, 256>>>(W3, Ws, invN);                   // 6
    final_kernel<<<N / 16, 256>>>(bs, out);                       // 7
}

// round 7
// speedup vs baseline: 1.7018x; 1.7018x over previous
#include <cuda_runtime.h>
#include <cuda_fp16.h>
#include <mma.h>
#include <cstdint>

using namespace nvcuda;

#define D   512
#define E   16
#define H1  128
#define H2  64
#define R   32
#define C1  (E * H1)   // 2048
#define C2  (E * H2)   // 1024
#define NMAX 65536

// ---------------- scratch (device globals: allocation-free) ----------------
__device__ __half g_x16[(size_t)NMAX * D];        // 64 MB
__device__ __half g_W1p[(size_t)D * C1];          // 2 MB   [d][e*128+j]
__device__ __half g_W2h[(size_t)E * H1 * H2];     // 256 KB [e][k][j]
__device__ __half g_h1[(size_t)NMAX * C1];        // 256 MB
__device__ __half g_h2[(size_t)NMAX * C2];        // 128 MB
__device__ float  g_gate[(size_t)NMAX * E];       // 4 MB
__device__ float  g_sum1[C1], g_ssq1[C1], g_mean1[C1], g_inv1[C1];
__device__ float  g_sum2[C2], g_ssq2[C2], g_mean2[C2], g_inv2[C2];
__device__ float  g_v[C2];

// ---------------- cp.async helpers ----------------
__device__ __forceinline__ void cp_async16(void* smem, const void* gmem) {
    unsigned int s = (unsigned int)__cvta_generic_to_shared(smem);
    asm volatile("cp.async.cg.shared.global [%0], [%1], 16;\n" :: "r"(s), "l"(gmem));
}
__device__ __forceinline__ void cp_commit() {
    asm volatile("cp.async.commit_group;\n");
}
template <int NN>
__device__ __forceinline__ void cp_wait() {
    asm volatile("cp.async.wait_group %0;\n" :: "n"(NN));
}

// ---------------- 0: pack weights fp16 + zero stats ----------------
__global__ void __launch_bounds__(256) pack_W_zero(const float* __restrict__ W1,
                                                   const float* __restrict__ W2) {
    int idx = blockIdx.x * 256 + threadIdx.x;   // grid 4096 -> 1048576
    if (idx < E * D * H1) {
        int j = idx & (H1 - 1);
        int d = (idx >> 7) & (D - 1);
        int e = idx >> 16;
        g_W1p[(size_t)d * C1 + e * H1 + j] = __float2half_rn(W1[idx]);
    }
    if (idx < E * H1 * H2) g_W2h[idx] = __float2half_rn(W2[idx]);
    if (idx < C1) { g_sum1[idx] = 0.f; g_ssq1[idx] = 0.f; }
    if (idx < C2) { g_sum2[idx] = 0.f; g_ssq2[idx] = 0.f; }
}

// ---------------- 1: convert x -> fp16 + gating (one pass over x) ----------------
__global__ void __launch_bounds__(256) convert_gate(
    const float* __restrict__ x, const float* __restrict__ Wg,
    const float* __restrict__ bg, const float* __restrict__ gamma_,
    const float* __restrict__ beta_) {
    __shared__ float xs[16 * D];   // 32 KB
    const int tid = threadIdx.x;
    const size_t row0 = (size_t)blockIdx.x * 16;

    const float4* xg = reinterpret_cast<const float4*>(x + row0 * D);
    float4* xsv = reinterpret_cast<float4*>(xs);
    __half* xo = g_x16 + row0 * D;
#pragma unroll
    for (int i = 0; i < 8; ++i) {
        int c = tid + i * 256;          // 0..2047 float4s
        float4 v = xg[c];
        xsv[c] = v;
        __half2 h0 = __floats2half2_rn(v.x, v.y);
        __half2 h1 = __floats2half2_rn(v.z, v.w);
        *reinterpret_cast<__half2*>(xo + 4 * c) = h0;
        *reinterpret_cast<__half2*>(xo + 4 * c + 2) = h1;
    }
    __syncthreads();

    const int e = tid & 15, r = tid >> 4;
    float g = 0.f;
#pragma unroll 8
    for (int d = 0; d < D; ++d) g += xs[r * D + d] * Wg[d * E + e];
    g += bg[e];

    float mu = g;
#pragma unroll
    for (int o = 8; o; o >>= 1) mu += __shfl_xor_sync(0xffffffffu, mu, o, 16);
    mu *= (1.f / 16.f);
    float dv = g - mu;
    float vv = dv * dv;
#pragma unroll
    for (int o = 8; o; o >>= 1) vv += __shfl_xor_sync(0xffffffffu, vv, o, 16);
    vv *= (1.f / 16.f);
    g = dv * rsqrtf(vv + 1e-5f) * gamma_[e] + beta_[e];

    float mx = g;
#pragma unroll
    for (int o = 8; o; o >>= 1) mx = fmaxf(mx, __shfl_xor_sync(0xffffffffu, mx, o, 16));
    float ex = __expf(g - mx);
    float s = ex;
#pragma unroll
    for (int o = 8; o; o >>= 1) s += __shfl_xor_sync(0xffffffffu, s, o, 16);
    g_gate[(row0 + r) * E + e] = ex / s;
}

// ---------------- 2: v = W3 @ Ws ----------------
__global__ void __launch_bounds__(256) compute_v(const float* __restrict__ W3,
                                                 const float* __restrict__ Ws) {
    __shared__ float wsm[R];
    const int tid = threadIdx.x;
    const int i = blockIdx.x * 256 + tid;   // grid 4 -> 0..1023
    if (tid < R) wsm[tid] = Ws[tid];
    __syncthreads();
    float v = 0.f;
#pragma unroll
    for (int r = 0; r < R; ++r) v = fmaf(W3[(size_t)i * R + r], wsm[r], v);
    g_v[i] = v;
}

// ---------------- 3: GEMM1 h1 = x16 @ W1p (65536x2048x512), PROFILED ----------------
// grid (16, 512): blockIdx.x = ntile (fastest -> 16 CTAs share x tile in L2),
// blockIdx.y = mtile. 128x128 tile, KTILE=64, 3-stage cp.async ring.
// Stage: A 128x64 (stride 72) 18432 B + B 64x128 (stride 136) 17408 B = 35840 B.
#define G1_STAGE 35840
#define G1_SMEM  (3 * G1_STAGE)   // 107520; Cs fp32 128x132 = 67584 reuses stage area

__global__ void __launch_bounds__(256) gemm1_kernel() {
    extern __shared__ char smbuf[];
    const int n0 = blockIdx.x * 128;
    const size_t m0 = (size_t)blockIdx.y * 128;
    const int tid = threadIdx.x;
    const int warp = tid >> 5;
    const int wm = warp & 3;    // 4 warps over M
    const int wn = warp >> 2;   // 2 warps over N

    wmma::fragment<wmma::accumulator, 16, 16, 16, float> acc[2][4];
#pragma unroll
    for (int i = 0; i < 2; ++i)
#pragma unroll
        for (int j = 0; j < 4; ++j) wmma::fill_fragment(acc[i][j], 0.0f);

    auto issue = [&](int kt, int s) {
        const int k0 = kt * 64;
        __half* A = reinterpret_cast<__half*>(smbuf + s * G1_STAGE);
        __half* B = A + 9216;   // 128*72 halves
#pragma unroll
        for (int i = 0; i < 4; ++i) {
            int c = tid + i * 256;            // 0..1023
            int r = c >> 3, off = (c & 7) * 8;
            cp_async16(A + r * 72 + off, g_x16 + (m0 + r) * D + k0 + off);
        }
#pragma unroll
        for (int i = 0; i < 4; ++i) {
            int c = tid + i * 256;
            int r = c >> 4, off = (c & 15) * 8;
            cp_async16(B + r * 136 + off, g_W1p + (size_t)(k0 + r) * C1 + n0 + off);
        }
        cp_commit();
    };

    issue(0, 0);
    issue(1, 1);
    issue(2, 2);

    for (int kt = 0; kt < 8; ++kt) {
        const int s = kt % 3;
        if (kt < 6) cp_wait<2>(); else if (kt == 6) cp_wait<1>(); else cp_wait<0>();
        __syncthreads();

        const __half* A = reinterpret_cast<const __half*>(smbuf + s * G1_STAGE);
        const __half* B = A + 9216;
#pragma unroll
        for (int kk = 0; kk < 4; ++kk) {
            wmma::fragment<wmma::matrix_a, 16, 16, 16, __half, wmma::row_major> af[2];
            wmma::fragment<wmma::matrix_b, 16, 16, 16, __half, wmma::row_major> bf[4];
#pragma unroll
            for (int i = 0; i < 2; ++i)
                wmma::load_matrix_sync(af[i], A + (wm * 32 + i * 16) * 72 + kk * 16, 72);
#pragma unroll
            for (int j = 0; j < 4; ++j)
                wmma::load_matrix_sync(bf[j], B + (kk * 16) * 136 + wn * 64 + j * 16, 136);
#pragma unroll
            for (int i = 0; i < 2; ++i)
#pragma unroll
                for (int j = 0; j < 4; ++j)
                    wmma::mma_sync(acc[i][j], af[i], bf[j], acc[i][j]);
        }
        __syncthreads();
        if (kt + 3 < 8) issue(kt + 3, s);
    }

    // ---- epilogue: C -> smem, fused BN1 stats atomics, fp16 h1 store ----
    __syncthreads();
    float* Cs = reinterpret_cast<float*>(smbuf);   // [128][132]
#pragma unroll
    for (int i = 0; i < 2; ++i)
#pragma unroll
        for (int j = 0; j < 4; ++j)
            wmma::store_matrix_sync(Cs + (wm * 32 + i * 16) * 132 + wn * 64 + j * 16,
                                    acc[i][j], 132, wmma::mem_row_major);
    __syncthreads();

    {
        int c = tid & 127, hf = tid >> 7;
        float s = 0.f, q = 0.f;
#pragma unroll 8
        for (int r = hf * 64; r < hf * 64 + 64; ++r) {
            float v = Cs[r * 132 + c];
            s += v;
            q = fmaf(v, v, q);
        }
        atomicAdd(&g_sum1[n0 + c], s);
        atomicAdd(&g_ssq1[n0 + c], q);
    }

#pragma unroll
    for (int i = 0; i < 32; ++i) {
        int pid = tid + i * 256;
        int r = pid >> 6, c2 = pid & 63;
        __half2 h = __floats2half2_rn(Cs[r * 132 + 2 * c2], Cs[r * 132 + 2 * c2 + 1]);
        *reinterpret_cast<__half2*>(g_h1 + (m0 + r) * C1 + n0 + 2 * c2) = h;
    }
}

// ---------------- 4/6: finalize BN stats ----------------
template <int NCOLS>
__global__ void finalize_kernel(float invN) {
    int c = blockIdx.x * 256 + threadIdx.x;
    if (c < NCOLS) {
        const float* sum = (NCOLS == C1) ? g_sum1 : g_sum2;
        const float* ssq = (NCOLS == C1) ? g_ssq1 : g_ssq2;
        float* mean = (NCOLS == C1) ? g_mean1 : g_mean2;
        float* inv  = (NCOLS == C1) ? g_inv1  : g_inv2;
        float m = sum[c] * invN;
        float var = fmaxf(ssq[c] * invN - m * m, 0.f);
        mean[c] = m;
        inv[c] = rsqrtf(var + 1e-4f);
    }
}

// ---------------- 5: GEMM2 h2 = bn_lrelu(h1[e]) @ W2[e], K=128 one-shot ----------------
#define G2_A_BYTES (128 * 136 * 2)   // 34816
#define G2_B_BYTES (128 * 72 * 2)    // 18432
#define G2_SMEM (G2_A_BYTES + G2_B_BYTES + 128 * 2 * 4)  // 54272

__global__ void __launch_bounds__(256) gemm2_kernel() {
    extern __shared__ char smbuf[];
    const int e = blockIdx.x;
    const size_t m0 = (size_t)blockIdx.y * 128;
    const int tid = threadIdx.x;

    __half* A = reinterpret_cast<__half*>(smbuf);                 // [128][136]
    __half* B = reinterpret_cast<__half*>(smbuf + G2_A_BYTES);    // [128][72]
    float* msh = reinterpret_cast<float*>(smbuf + G2_A_BYTES + G2_B_BYTES);
    float* ish = msh + 128;

#pragma unroll
    for (int i = 0; i < 8; ++i) {
        int c = tid + i * 256;
        int r = c >> 4, col = (c & 15) * 8;
        cp_async16(A + r * 136 + col, g_h1 + (m0 + r) * C1 + e * H1 + col);
    }
#pragma unroll
    for (int i = 0; i < 4; ++i) {
        int c = tid + i * 256;
        int r = c >> 3, col = (c & 7) * 8;
        cp_async16(B + r * 72 + col, g_W2h + (size_t)e * (H1 * H2) + r * H2 + col);
    }
    cp_commit();
    if (tid < 128) {
        msh[tid] = g_mean1[e * H1 + tid];
        ish[tid] = g_inv1[e * H1 + tid];
    }
    cp_wait<0>();
    __syncthreads();

#pragma unroll
    for (int i = 0; i < 32; ++i) {
        int pid = tid + i * 256;
        int r = pid >> 6, c2 = pid & 63;
        __half2* p = reinterpret_cast<__half2*>(A + r * 136 + 2 * c2);
        float2 v = __half22float2(*p);
        float a0 = (v.x - msh[2 * c2]) * ish[2 * c2];
        float a1 = (v.y - msh[2 * c2 + 1]) * ish[2 * c2 + 1];
        a0 = (a0 >= 0.f) ? a0 : 0.01f * a0;
        a1 = (a1 >= 0.f) ? a1 : 0.01f * a1;
        *p = __floats2half2_rn(a0, a1);
    }
    __syncthreads();

    const int warp = tid >> 5;
    const int wm = warp & 3;
    const int wn = warp >> 2;

    wmma::fragment<wmma::accumulator, 16, 16, 16, float> acc[2][2];
#pragma unroll
    for (int i = 0; i < 2; ++i)
#pragma unroll
        for (int j = 0; j < 2; ++j) wmma::fill_fragment(acc[i][j], 0.0f);

#pragma unroll
    for (int kk = 0; kk < 8; ++kk) {
        wmma::fragment<wmma::matrix_a, 16, 16, 16, __half, wmma::row_major> af[2];
        wmma::fragment<wmma::matrix_b, 16, 16, 16, __half, wmma::row_major> bf[2];
#pragma unroll
        for (int i = 0; i < 2; ++i)
            wmma::load_matrix_sync(af[i], A + (wm * 32 + i * 16) * 136 + kk * 16, 136);
#pragma unroll
        for (int j = 0; j < 2; ++j)
            wmma::load_matrix_sync(bf[j], B + (kk * 16) * 72 + wn * 32 + j * 16, 72);
#pragma unroll
        for (int i = 0; i < 2; ++i)
#pragma unroll
            for (int j = 0; j < 2; ++j)
                wmma::mma_sync(acc[i][j], af[i], bf[j], acc[i][j]);
    }

    __syncthreads();
    float* Cs = reinterpret_cast<float*>(smbuf);  // [128][68]
#pragma unroll
    for (int i = 0; i < 2; ++i)
#pragma unroll
        for (int j = 0; j < 2; ++j)
            wmma::store_matrix_sync(Cs + (wm * 32 + i * 16) * 68 + wn * 32 + j * 16,
                                    acc[i][j], 68, wmma::mem_row_major);
    __syncthreads();

    {
        int c = tid & 63, q4 = tid >> 6;
        float s = 0.f, q = 0.f;
#pragma unroll 8
        for (int r = q4 * 32; r < q4 * 32 + 32; ++r) {
            float v = Cs[r * 68 + c];
            s += v;
            q = fmaf(v, v, q);
        }
        atomicAdd(&g_sum2[e * H2 + c], s);
        atomicAdd(&g_ssq2[e * H2 + c], q);
    }

#pragma unroll
    for (int i = 0; i < 16; ++i) {
        int pid = tid + i * 256;
        int r = pid >> 5, c2 = pid & 31;
        __half2 h = __floats2half2_rn(Cs[r * 68 + 2 * c2], Cs[r * 68 + 2 * c2 + 1]);
        *reinterpret_cast<__half2*>(g_h2 + (m0 + r) * C2 + e * H2 + 2 * c2) = h;
    }
}

// ---------------- 7: final combine ----------------
__global__ void __launch_bounds__(256) final_kernel(const float* __restrict__ bs_p,
                                                    float* __restrict__ out) {
    const int tid = threadIdx.x;
    const int e = tid & 15, r = tid >> 4;
    const size_t row = (size_t)blockIdx.x * 16 + r;

    const uint4* hp = reinterpret_cast<const uint4*>(g_h2 + row * C2 + (size_t)e * H2);
    const float* mp = g_mean2 + e * H2;
    const float* ip = g_inv2 + e * H2;
    const float* vp = g_v + e * H2;

    float acc = 0.f;
#pragma unroll
    for (int i = 0; i < 8; ++i) {      // 8 uint4 = 64 halves
        uint4 q = hp[i];
        unsigned vals[4] = {q.x, q.y, q.z, q.w};
#pragma unroll
        for (int j = 0; j < 4; ++j) {
            __half2 h2 = *reinterpret_cast<__half2*>(&vals[j]);
            float2 f = __half22float2(h2);
            int k = i * 8 + j * 2;
            float a0 = (f.x - mp[k]) * ip[k];
            float a1 = (f.y - mp[k + 1]) * ip[k + 1];
            a0 = (a0 >= 0.f) ? a0 : 0.01f * a0;
            a1 = (a1 >= 0.f) ? a1 : 0.01f * a1;
            acc = fmaf(a0, vp[k], acc);
            acc = fmaf(a1, vp[k + 1], acc);
        }
    }
    float contrib = g_gate[row * E + e] * (acc + bs_p[0]);
#pragma unroll
    for (int o = 8; o; o >>= 1) contrib += __shfl_down_sync(0xffffffffu, contrib, o, 16);
    if (e == 0) out[row] = contrib;
}

// ---------------- launch ----------------
extern "C" void kernel_launch(void* const* d_in, const int* in_sizes, int n_in,
                              void* d_out, int out_size) {
    const float* x  = (const float*)d_in[0];
    const float* Wg = (const float*)d_in[1];
    const float* bg = (const float*)d_in[2];
    const float* ga = (const float*)d_in[3];
    const float* be = (const float*)d_in[4];
    const float* W1 = (const float*)d_in[5];
    const float* W2 = (const float*)d_in[6];
    const float* W3 = (const float*)d_in[7];
    const float* Ws = (const float*)d_in[8];
    const float* bs = (const float*)d_in[9];
    float* out = (float*)d_out;

    const int N = in_sizes[0] / D;        // 65536
    const int mtiles = N / 128;           // 512
    const float invN = 1.0f / (float)N;

    static bool attr_done = false;
    if (!attr_done) {
        cudaFuncSetAttribute(gemm1_kernel, cudaFuncAttributeMaxDynamicSharedMemorySize, G1_SMEM);
        cudaFuncSetAttribute(gemm2_kernel, cudaFuncAttributeMaxDynamicSharedMemorySize, G2_SMEM);
        attr_done = true;
    }

    pack_W_zero<<<4096, 256>>>(W1, W2);                           // 0
    convert_gate<<<N / 16, 256>>>(x, Wg, bg, ga, be);             // 1
    compute_v<<<4, 256>>>(W3, Ws);                                // 2
    gemm1_kernel<<<dim3(C1 / 128, mtiles), 256, G1_SMEM>>>();     // 3 (PROFILED)
    finalize_kernel<C1><<<8, 256>>>(invN);                        // 4
    gemm2_kernel<<<dim3(E, mtiles), 256, G2_SMEM>>>();            // 5
    finalize_kernel<C2><<<4, 256>>>(invN);                        // 6
    final_kernel<<<N / 16, 256>>>(bs, out);                       // 7
}